// round 2
// baseline (speedup 1.0000x reference)
#include <cuda_runtime.h>
#include <cstdint>

// p-bit Glauber sequential update, N=4096 spins, 16384 steps.
//   Kernel 0 (parallel): thr[t] = atanhf(2*u[t]-1), zipped with idx[t] into float2.
//     Decision "tanh(F) >= r" == "F >= atanh(r)" (monotone); removes all MUFU
//     work from the sequential critical path.
//   Kernel 1 (parallel): F[j] = h[j] + dot(J[j,:], m0); warms L2 with J (64MB < 126MB L2).
//   Kernel 2 (single CTA): window-speculative sequential dynamics.
//     Evaluate 512 future steps in parallel assuming no flip; ballot to find the
//     first step whose spin changes; apply that flip (rank-1 update F += 2s*J[i,:],
//     16KB row from L2) and continue after it.

#define NN      4096
#define NSTEPS  16384
#define TPB     512
#define NWARPS  (TPB / 32)
#define CHUNKS  (NN / 4 / TPB)   // float4 chunks of F per thread in row update (=2)

__device__ float  g_F[NN];
__device__ float2 g_TI[NSTEPS];   // {thr = atanh(2u-1), idx-as-float-bits}

// ---------------------------------------------------------------------------
// Kernel 0: thresholds
// ---------------------------------------------------------------------------
__global__ void prep_thresholds(const int* __restrict__ idx,
                                const float* __restrict__ u) {
    const int t = blockIdx.x * blockDim.x + threadIdx.x;
    if (t < NSTEPS) {
        const float r = 2.0f * u[t] - 1.0f;   // 2u exact -> single rounding, same as ref
        g_TI[t] = make_float2(atanhf(r), __int_as_float(idx[t]));
    }
}

// ---------------------------------------------------------------------------
// Kernel 1: initial local fields F = J @ m0 + h   (one block per row)
// ---------------------------------------------------------------------------
__global__ void init_field(const float* __restrict__ J,
                           const float* __restrict__ h,
                           const float* __restrict__ m0) {
    const int row = blockIdx.x;
    const float4* __restrict__ Jr = reinterpret_cast<const float4*>(J) + (size_t)row * (NN / 4);
    const float4* __restrict__ M4 = reinterpret_cast<const float4*>(m0);

    float sum = 0.0f;
    for (int k = threadIdx.x; k < NN / 4; k += blockDim.x) {
        float4 a = Jr[k];
        float4 b = M4[k];
        sum += a.x * b.x;
        sum += a.y * b.y;
        sum += a.z * b.z;
        sum += a.w * b.w;
    }
    #pragma unroll
    for (int off = 16; off; off >>= 1)
        sum += __shfl_xor_sync(0xffffffffu, sum, off);

    __shared__ float ws[8];
    const int lane = threadIdx.x & 31;
    const int wid  = threadIdx.x >> 5;
    if (lane == 0) ws[wid] = sum;
    __syncthreads();
    if (threadIdx.x == 0) {
        float tot = 0.0f;
        #pragma unroll
        for (int w = 0; w < 8; w++) tot += ws[w];
        g_F[row] = tot + h[row];
    }
}

// ---------------------------------------------------------------------------
// Kernel 2: sequential dynamics with window speculation (single CTA)
// ---------------------------------------------------------------------------
__global__ __launch_bounds__(TPB, 1)
void pbit_dynamics(const float* __restrict__ J,
                   const float* __restrict__ m0,
                   float*       __restrict__ out) {
    __shared__ float F_sh[NN];                       // 16 KB local fields
    __shared__ float m_sh[NN];                       // 16 KB spins (+-1)
    __shared__ __align__(16) unsigned flip_bal[NWARPS];
    __shared__ __align__(16) unsigned sign_bal[NWARPS];

    const int tid  = threadIdx.x;
    const int lane = tid & 31;
    const int wid  = tid >> 5;

    for (int k = tid; k < NN; k += TPB) {
        F_sh[k] = g_F[k];
        m_sh[k] = m0[k];
    }
    __syncthreads();

    int t = 0;
    while (t < NSTEPS) {
        // ---- epoch 1: speculative evaluation of window [t, t+TPB) ----
        const int tt = t + tid;
        bool  flip = false;
        bool  spos = false;
        int   i_ev = 0;
        if (tt < NSTEPS) {
            const float2 ti = g_TI[tt];
            const int i = __int_as_float(0), _unused = 0; (void)_unused;
            const int ii = __float_as_int(ti.y);
            spos = (F_sh[ii] >= ti.x);               // == (tanh(F) >= r)
            flip = spos != (m_sh[ii] > 0.0f);
            i_ev = ii;
        }
        const unsigned fb = __ballot_sync(0xffffffffu, flip);
        const unsigned sb = __ballot_sync(0xffffffffu, spos);
        if (lane == 0) { flip_bal[wid] = fb; sign_bal[wid] = sb; }
        __syncthreads();

        // ---- epoch 2: first flipping position + rank-1 update ----
        int f = -1;
        #pragma unroll
        for (int w = NWARPS - 1; w >= 0; w--) {
            const unsigned b = flip_bal[w];
            if (b) f = (w << 5) + (__ffs(b) - 1);
        }

        if (f >= 0) {
            const int Tstep = t + f;
            const int i = __float_as_int(g_TI[Tstep].y);     // uniform -> broadcast
            const float s = ((sign_bal[f >> 5] >> (f & 31)) & 1u) ? 1.0f : -1.0f;
            const float d = 2.0f * s;                        // delta = s - (-s)

            // rank-1 field update: F += d * J[i,:]   (16 KB row, L2 resident)
            const float4* __restrict__ Jr =
                reinterpret_cast<const float4*>(J) + (size_t)i * (NN / 4);
            float4* Fv = reinterpret_cast<float4*>(F_sh);
            #pragma unroll
            for (int c = 0; c < CHUNKS; c++) {
                const int k = tid + c * TPB;
                const float4 a = Jr[k];
                float4 fv = Fv[k];
                fv.x += a.x * d;
                fv.y += a.y * d;
                fv.z += a.z * d;
                fv.w += a.w * d;
                Fv[k] = fv;
            }
            if (tid == f) m_sh[i_ev] = s;    // sole writer; readers bar-separated
            t = Tstep + 1;
        } else {
            t += TPB;                        // whole window clean
        }
        __syncthreads();
    }

    for (int k = tid; k < NN; k += TPB)
        out[k] = m_sh[k];
}

// ---------------------------------------------------------------------------
extern "C" void kernel_launch(void* const* d_in, const int* in_sizes, int n_in,
                              void* d_out, int out_size) {
    const float* J  = (const float*)d_in[0];   // 4096*4096 f32
    const float* h  = (const float*)d_in[1];   // 4096 f32
    const float* m0 = (const float*)d_in[2];   // 4096 f32
    const int*   idx= (const int*)  d_in[3];   // 16384 i32
    const float* u  = (const float*)d_in[4];   // 16384 f32
    float* out = (float*)d_out;                // 4096 f32

    prep_thresholds<<<NSTEPS / 256, 256>>>(idx, u);
    init_field<<<NN, 256>>>(J, h, m0);
    pbit_dynamics<<<1, TPB>>>(J, m0, out);
}

// round 3
// speedup vs baseline: 1.3532x; 1.3532x over previous
#include <cuda_runtime.h>
#include <cstdint>

// p-bit Glauber sequential update, N=4096 spins, 16384 steps.
// K0: thr[t]=atanh(2u-1) zipped with idx  (tanh(F)>=r  <=>  F>=atanh(r))
// K1: F = J@m0 + h (parallel, warms L2 with 64MB J)
// K2: single-CTA anchored-window speculation:
//     window of 512 steps lives in registers (thr, idx, spin copy);
//     per round: ballot -> first flip f1 + candidate f2; apply rank-1 row
//     update for f1 (row prefetched last round if f1 was predicted),
//     prefetch row for f2; re-evaluate only threads > f1.

#define NN      4096
#define NSTEPS  16384
#define TPB     512
#define NWARPS  (TPB / 32)

__device__ float  g_F[NN];
__device__ float2 g_TI[NSTEPS];   // {thr, idx-as-float-bits}

// ---------------------------------------------------------------------------
__global__ void prep_thresholds(const int* __restrict__ idx,
                                const float* __restrict__ u) {
    const int t = blockIdx.x * blockDim.x + threadIdx.x;
    if (t < NSTEPS) {
        const float r = 2.0f * u[t] - 1.0f;
        g_TI[t] = make_float2(atanhf(r), __int_as_float(idx[t]));
    }
}

// ---------------------------------------------------------------------------
__global__ void init_field(const float* __restrict__ J,
                           const float* __restrict__ h,
                           const float* __restrict__ m0) {
    const int row = blockIdx.x;
    const float4* __restrict__ Jr = reinterpret_cast<const float4*>(J) + (size_t)row * (NN / 4);
    const float4* __restrict__ M4 = reinterpret_cast<const float4*>(m0);

    float sum = 0.0f;
    for (int k = threadIdx.x; k < NN / 4; k += blockDim.x) {
        float4 a = Jr[k];
        float4 b = M4[k];
        sum += a.x * b.x + a.y * b.y + a.z * b.z + a.w * b.w;
    }
    #pragma unroll
    for (int off = 16; off; off >>= 1)
        sum += __shfl_xor_sync(0xffffffffu, sum, off);

    __shared__ float ws[8];
    const int lane = threadIdx.x & 31;
    const int wid  = threadIdx.x >> 5;
    if (lane == 0) ws[wid] = sum;
    __syncthreads();
    if (threadIdx.x == 0) {
        float tot = 0.0f;
        #pragma unroll
        for (int w = 0; w < 8; w++) tot += ws[w];
        g_F[row] = tot + h[row];
    }
}

// ---------------------------------------------------------------------------
__global__ __launch_bounds__(TPB, 1)
void pbit_dynamics(const float* __restrict__ J,
                   const float* __restrict__ m0,
                   float*       __restrict__ out) {
    __shared__ float F_sh[NN];
    __shared__ float m_sh[NN];
    __shared__ int   win_idx[TPB];
    __shared__ __align__(16) unsigned fbal[NWARPS];
    __shared__ __align__(16) unsigned sbal[NWARPS];

    const int tid  = threadIdx.x;
    const int lane = tid & 31;
    const int wid  = tid >> 5;

    for (int k = tid; k < NN; k += TPB) {
        F_sh[k] = g_F[k];
        m_sh[k] = m0[k];
    }
    __syncthreads();

    for (int t = 0; t < NSTEPS; t += TPB) {
        // ---- window load: everything into registers, once ----
        const float2 ti = g_TI[t + tid];
        const float my_thr = ti.x;
        const int   my_i   = __float_as_int(ti.y);
        win_idx[tid] = my_i;
        float my_m = m_sh[my_i];                  // register copy of my spin

        bool spos = (F_sh[my_i] >= my_thr);       // == (tanh(F) >= r)
        bool flip = spos != (my_m > 0.0f);
        unsigned fb = __ballot_sync(0xffffffffu, flip);
        unsigned sb = __ballot_sync(0xffffffffu, spos);
        if (lane == 0) { fbal[wid] = fb; sbal[wid] = sb; }
        __syncthreads();

        int    pf_f = -1;                         // predicted next flip pos
        float4 p0, p1;                            // prefetched row chunks

        for (;;) {
            // ---- scan ballots for first two flip positions ----
            int f1 = -1, f2 = -1;
            #pragma unroll
            for (int w = 0; w < NWARPS; w++) {
                unsigned b = fbal[w];
                if (b) {
                    if (f1 < 0) {
                        f1 = (w << 5) + __ffs(b) - 1;
                        b &= b - 1;
                        if (b) f2 = (w << 5) + __ffs(b) - 1;
                    } else if (f2 < 0) {
                        f2 = (w << 5) + __ffs(b) - 1;
                    }
                }
            }
            if (f1 < 0) break;                    // window clean

            const int   i1 = win_idx[f1];
            const float s1 = ((sbal[f1 >> 5] >> (f1 & 31)) & 1u) ? 1.0f : -1.0f;
            const float d  = 2.0f * s1;

            float4 r0, r1;
            if (pf_f == f1) {                     // speculation hit: row in regs
                r0 = p0; r1 = p1;
            } else {                              // miss: blocking fetch
                const float4* __restrict__ Jr =
                    reinterpret_cast<const float4*>(J) + (size_t)i1 * (NN / 4);
                r0 = Jr[tid];
                r1 = Jr[tid + TPB];
            }
            // issue prefetch for candidate f2 before consuming r0/r1
            if (f2 >= 0) {
                const int i2 = win_idx[f2];
                const float4* __restrict__ Jp =
                    reinterpret_cast<const float4*>(J) + (size_t)i2 * (NN / 4);
                p0 = Jp[tid];
                p1 = Jp[tid + TPB];
                pf_f = f2;
            } else {
                pf_f = -1;
            }

            // ---- rank-1 update: F += d * J[i1,:] ----
            float4* Fv = reinterpret_cast<float4*>(F_sh);
            float4 a = Fv[tid];
            a.x += r0.x * d; a.y += r0.y * d; a.z += r0.z * d; a.w += r0.w * d;
            Fv[tid] = a;
            float4 b2 = Fv[tid + TPB];
            b2.x += r1.x * d; b2.y += r1.y * d; b2.z += r1.z * d; b2.w += r1.w * d;
            Fv[tid + TPB] = b2;

            if (my_i == i1) my_m = s1;            // all duplicate-index threads
            if (tid == f1)  m_sh[i1] = s1;        // persistent spin store
            __syncthreads();

            // ---- re-evaluate only unresolved steps ----
            bool spos2 = false, flip2 = false;
            if (tid > f1) {
                spos2 = (F_sh[my_i] >= my_thr);
                flip2 = spos2 != (my_m > 0.0f);
            }
            fb = __ballot_sync(0xffffffffu, flip2);
            sb = __ballot_sync(0xffffffffu, spos2);
            if (lane == 0) { fbal[wid] = fb; sbal[wid] = sb; }
            __syncthreads();
        }
    }

    for (int k = tid; k < NN; k += TPB)
        out[k] = m_sh[k];
}

// ---------------------------------------------------------------------------
extern "C" void kernel_launch(void* const* d_in, const int* in_sizes, int n_in,
                              void* d_out, int out_size) {
    const float* J  = (const float*)d_in[0];
    const float* h  = (const float*)d_in[1];
    const float* m0 = (const float*)d_in[2];
    const int*   idx= (const int*)  d_in[3];
    const float* u  = (const float*)d_in[4];
    float* out = (float*)d_out;

    prep_thresholds<<<NSTEPS / 256, 256>>>(idx, u);
    init_field<<<NN, 256>>>(J, h, m0);
    pbit_dynamics<<<1, TPB>>>(J, m0, out);
}